// round 2
// baseline (speedup 1.0000x reference)
#include <cuda_runtime.h>

#define NU 8192
#define NC 8192
#define NK 8192
#define D  32

// ---------------- scratch (static __device__, no allocation) ----------------
__device__ float g_T0[NU * D];        // dinv_uu ⊙ (X_U @ weight_s)
__device__ float g_T1[NC * D];        // dinv_cc ⊙ (X_C @ weight_s)
__device__ float g_T2[NU * D];        // dc ⊙ ((X_U @ proj_u) @ weight_c)
__device__ float g_c1[NC * D];        // node_embed_c1
__device__ float g_c2[NC * D];        // node_embed_c2
__device__ float g_dinv_uu[NU];
__device__ float g_dinv_cc[NC];
__device__ float g_du[NU];
__device__ float g_dc[NC];
__device__ float g_colpart[512 * NC]; // per-block colsum partials for adj_uc
__device__ float g_W2[D * D];         // proj_u @ weight_c

// ---------------- packed f32x2 helpers ----------------
__device__ __forceinline__ unsigned long long ffma2(
    unsigned long long a, unsigned long long b, unsigned long long c) {
    unsigned long long d;
    asm("fma.rn.f32x2 %0, %1, %2, %3;" : "=l"(d) : "l"(a), "l"(b), "l"(c));
    return d;
}
__device__ __forceinline__ unsigned long long bcast2(float x) {
    unsigned long long r;
    asm("mov.b64 %0, {%1, %1};" : "=l"(r) : "f"(x));
    return r;
}
__device__ __forceinline__ float lo32(unsigned long long v) {
    return __uint_as_float((unsigned)(v & 0xffffffffull));
}
__device__ __forceinline__ float hi32(unsigned long long v) {
    return __uint_as_float((unsigned)(v >> 32));
}

// ---------------- tiny: W2 = proj_u @ weight_c ----------------
__global__ void k_w2(const float* __restrict__ proj_u,
                     const float* __restrict__ weight_c) {
    int i = threadIdx.x >> 5;
    int j = threadIdx.x & 31;
    float s = 0.f;
#pragma unroll
    for (int k = 0; k < 32; k++) s += proj_u[i * 32 + k] * weight_c[k * 32 + j];
    g_W2[i * 32 + j] = s;
}

// ---------------- rowsums for adj_uu / adj_cc -> rsqrt(1 + rowsum) ----------------
__global__ void k_rowsum(const float* __restrict__ adj_uu,
                         const float* __restrict__ adj_cc) {
    int row = blockIdx.x;
    const float* A = (blockIdx.y == 0) ? adj_uu : adj_cc;
    float* out = (blockIdx.y == 0) ? g_dinv_uu : g_dinv_cc;

    const float4* p = (const float4*)(A + (size_t)row * NK);
    float s = 0.f;
#pragma unroll
    for (int i = threadIdx.x; i < NK / 4; i += 256) {
        float4 v = p[i];
        s += (v.x + v.y) + (v.z + v.w);
    }
#pragma unroll
    for (int o = 16; o; o >>= 1) s += __shfl_xor_sync(0xffffffffu, s, o);
    __shared__ float sm[8];
    if ((threadIdx.x & 31) == 0) sm[threadIdx.x >> 5] = s;
    __syncthreads();
    if (threadIdx.x == 0) {
        float t = 0.f;
#pragma unroll
        for (int i = 0; i < 8; i++) t += sm[i];
        out[row] = rsqrtf(1.0f + t);
    }
}

// ---------------- adj_uc: rowsums -> du, colsum partials -> g_colpart ----------------
// 512 blocks x 16 rows each; one full-width pass over the matrix.
__global__ void k_uc_sums(const float* __restrict__ adj_uc) {
    int tid = threadIdx.x;  // 256
    int m0 = blockIdx.x * 16;
    float4 colacc[8];
#pragma unroll
    for (int i = 0; i < 8; i++) colacc[i] = make_float4(0.f, 0.f, 0.f, 0.f);
    __shared__ float sm[8];

    for (int r = 0; r < 16; r++) {
        const float4* p = (const float4*)(adj_uc + (size_t)(m0 + r) * NK);
        float rs = 0.f;
#pragma unroll
        for (int i = 0; i < 8; i++) {
            float4 v = p[tid + i * 256];
            colacc[i].x += v.x; colacc[i].y += v.y;
            colacc[i].z += v.z; colacc[i].w += v.w;
            rs += (v.x + v.y) + (v.z + v.w);
        }
#pragma unroll
        for (int o = 16; o; o >>= 1) rs += __shfl_xor_sync(0xffffffffu, rs, o);
        __syncthreads();  // protect sm reuse across iterations
        if ((tid & 31) == 0) sm[tid >> 5] = rs;
        __syncthreads();
        if (tid == 0) {
            float t = 0.f;
#pragma unroll
            for (int i = 0; i < 8; i++) t += sm[i];
            g_du[m0 + r] = rsqrtf(t);  // no +1 in gcn_c
        }
    }
    float4* cp = (float4*)(g_colpart + (size_t)blockIdx.x * NC);
#pragma unroll
    for (int i = 0; i < 8; i++) cp[tid + i * 256] = colacc[i];
}

// ---------------- deterministic colsum reduce -> dc ----------------
__global__ void k_dc() {
    int c = blockIdx.x * 256 + threadIdx.x;  // 32 blocks
    float s = 0.f;
    for (int r = 0; r < 512; r++) s += g_colpart[(size_t)r * NC + c];
    g_dc[c] = rsqrtf(s);  // no +1 in gcn_c
}

// ---------------- scaled supports T0/T1/T2 ----------------
__global__ void k_support(const float* __restrict__ X_U,
                          const float* __restrict__ X_C,
                          const float* __restrict__ weight_s) {
    __shared__ float Ws[1024];
    int which = blockIdx.y;
    int tid = threadIdx.x;  // 256
    if (which == 2) {
        for (int i = tid; i < 1024; i += 256) Ws[i] = g_W2[i];
    } else {
        for (int i = tid; i < 1024; i += 256) Ws[i] = weight_s[i];
    }
    __syncthreads();

    int row = blockIdx.x * 8 + (tid >> 5);
    int c = tid & 31;
    const float* X = (which == 1) ? X_C : X_U;
    const float* xr = X + (size_t)row * 32;
    float s = 0.f;
#pragma unroll
    for (int k = 0; k < 32; k++) s += xr[k] * Ws[k * 32 + c];

    float scale;
    float* T;
    if (which == 0)      { scale = g_dinv_uu[row]; T = g_T0; }
    else if (which == 1) { scale = g_dinv_cc[row]; T = g_T1; }
    else                 { scale = g_dc[row];      T = g_T2; }
    T[(size_t)row * 32 + c] = scale * s;
}

// ---------------- fused 3-way SpMM: out = rowscale ⊙ (A @ T) ----------------
// BM=32 rows/block, BK=32, 128 threads: thread -> (row r = tid>>2, colgroup g = tid&3, 8 cols)
// grid = 768 (3 matrices x 256 row-blocks) => all blocks resident, ~5/SM.
#define BM 32
#define BK 32
#define APITCH 36  // pad: conflict-free + 16B-aligned stores

__global__ void __launch_bounds__(128) k_spmm(
    const float* __restrict__ adj_uu, const float* __restrict__ adj_cc,
    const float* __restrict__ adj_uc, float* __restrict__ out_u) {
    int mat = blockIdx.x >> 8;
    int mb  = blockIdx.x & 255;

    const float* A;
    const float* T;
    const float* rowscale;
    float* out;
    if (mat == 0)      { A = adj_uu; T = g_T0; rowscale = g_dinv_uu; out = out_u; }
    else if (mat == 1) { A = adj_cc; T = g_T1; rowscale = g_dinv_cc; out = g_c1; }
    else               { A = adj_uc; T = g_T2; rowscale = g_du;      out = g_c2; }

    __shared__ float As[BM * APITCH];  // 4.6 KB
    __shared__ float Bs[BK * 32];      // 4 KB

    int tid = threadIdx.x;
    int r = tid >> 2;   // 0..31
    int g = tid & 3;    // 8 cols each

    int m0 = mb * BM;
    const float* Abase = A + (size_t)m0 * NK;

    unsigned long long acc0 = 0, acc1 = 0, acc2 = 0, acc3 = 0;

    for (int k0 = 0; k0 < NK; k0 += BK) {
        // stage A tile (32x32) and B tile (32x32), coalesced float4
        {
            int f = tid;
#pragma unroll
            for (int it = 0; it < 2; it++, f += 128) {
                int rr = f >> 3, kq = f & 7;
                float4 v = *(const float4*)(Abase + (size_t)rr * NK + k0 + kq * 4);
                *(float4*)(As + rr * APITCH + kq * 4) = v;
            }
            f = tid;
#pragma unroll
            for (int it = 0; it < 2; it++, f += 128) {
                int kk = f >> 3, cq = f & 7;
                *(float4*)(Bs + kk * 32 + cq * 4) =
                    *(const float4*)(T + (size_t)(k0 + kk) * 32 + cq * 4);
            }
        }
        __syncthreads();

        const float* arow = As + r * APITCH;
        const float* bcol = Bs + g * 8;
#pragma unroll
        for (int kk = 0; kk < BK; kk++) {
            unsigned long long a2 = bcast2(arow[kk]);
            ulonglong2 b01 = *(const ulonglong2*)(bcol + kk * 32);
            ulonglong2 b23 = *(const ulonglong2*)(bcol + kk * 32 + 4);
            acc0 = ffma2(a2, b01.x, acc0);
            acc1 = ffma2(a2, b01.y, acc1);
            acc2 = ffma2(a2, b23.x, acc2);
            acc3 = ffma2(a2, b23.y, acc3);
        }
        __syncthreads();
    }

    float sc = rowscale[m0 + r];
    float4 o0 = make_float4(sc * lo32(acc0), sc * hi32(acc0),
                            sc * lo32(acc1), sc * hi32(acc1));
    float4 o1 = make_float4(sc * lo32(acc2), sc * hi32(acc2),
                            sc * lo32(acc3), sc * hi32(acc3));
    float* orow = out + (size_t)(m0 + r) * 32 + g * 8;
    *(float4*)(orow) = o0;
    *(float4*)(orow + 4) = o1;
}

// ---------------- attention + softmax + outputs ----------------
__global__ void k_attn(const float* __restrict__ X_C,
                       const float* __restrict__ W_lin,
                       const float* __restrict__ a_vec,
                       float* __restrict__ out) {
    __shared__ float Ws[64 * 32];
    __shared__ float av[32];
    int tid = threadIdx.x;  // 256
    for (int i = tid; i < 2048; i += 256) Ws[i] = W_lin[i];
    if (tid < 32) av[tid] = a_vec[tid];
    __syncthreads();

    int lane = tid & 31;
    int row = blockIdx.x * 8 + (tid >> 5);

    float c1v = g_c1[(size_t)row * 32 + lane];
    float c2v = g_c2[(size_t)row * 32 + lane];
    float xcv = X_C[(size_t)row * 32 + lane];

    float h1 = 0.f, h2 = 0.f;
#pragma unroll
    for (int k = 0; k < 32; k++) {
        float u1 = __shfl_sync(0xffffffffu, c1v, k);
        float u2 = __shfl_sync(0xffffffffu, c2v, k);
        float w0 = Ws[k * 32 + lane];
        h1 = fmaf(u1, w0, h1);
        h2 = fmaf(u2, w0, h2);
    }
#pragma unroll
    for (int k = 0; k < 32; k++) {
        float ux = __shfl_sync(0xffffffffu, xcv, k);
        float w1 = Ws[(32 + k) * 32 + lane];
        h1 = fmaf(ux, w1, h1);
        h2 = fmaf(ux, w1, h2);
    }
    float t1 = fmaxf(h1, 0.f) * av[lane];
    float t2 = fmaxf(h2, 0.f) * av[lane];
#pragma unroll
    for (int o = 16; o; o >>= 1) {
        t1 += __shfl_xor_sync(0xffffffffu, t1, o);
        t2 += __shfl_xor_sync(0xffffffffu, t2, o);
    }
    float m = fmaxf(t1, t2);
    float e1 = expf(t1 - m), e2 = expf(t2 - m);
    float inv = 1.f / (e1 + e2);
    float yc = (e1 * inv) * c1v;
    float yu = (e2 * inv) * c2v;

    size_t idx = (size_t)row * 32 + lane;
    out[262144 + idx] = yc + yu;  // node_embed_c
    out[524288 + idx] = yc;       // Y_c
    out[786432 + idx] = yu;       // Y_u
}

// ---------------- launch ----------------
extern "C" void kernel_launch(void* const* d_in, const int* in_sizes, int n_in,
                              void* d_out, int out_size) {
    const float* X_U      = (const float*)d_in[0];
    const float* X_C      = (const float*)d_in[1];
    const float* adj_uu   = (const float*)d_in[2];
    const float* adj_uc   = (const float*)d_in[3];
    const float* adj_cc   = (const float*)d_in[4];
    const float* weight_s = (const float*)d_in[5];
    const float* proj_u   = (const float*)d_in[6];
    // d_in[7] = proj_c (unused in forward math)
    const float* weight_c = (const float*)d_in[8];
    const float* W_lin    = (const float*)d_in[9];
    const float* a_vec    = (const float*)d_in[10];
    float* out = (float*)d_out;

    k_w2<<<1, 1024>>>(proj_u, weight_c);
    k_rowsum<<<dim3(8192, 2), 256>>>(adj_uu, adj_cc);
    k_uc_sums<<<512, 256>>>(adj_uc);
    k_dc<<<32, 256>>>();
    k_support<<<dim3(1024, 3), 256>>>(X_U, X_C, weight_s);
    k_spmm<<<768, 128>>>(adj_uu, adj_cc, adj_uc, out);
    k_attn<<<1024, 256>>>(X_C, W_lin, a_vec, out);
}

// round 4
// speedup vs baseline: 1.6243x; 1.6243x over previous
#include <cuda_runtime.h>
#include <cstdint>

#define NU 8192
#define NC 8192
#define NK 8192
#define D  32

// ---------------- scratch ----------------
// B tiles per (mat, ktile): [hi 32x36 | lo 32x36] floats, tf32-prerounded, pad pitch 36
__device__ float g_Bt[3 * 256 * 2304];
__device__ float g_c1[NC * D];
__device__ float g_c2[NC * D];
__device__ float g_dinv_uu[NU];
__device__ float g_dinv_cc[NC];
__device__ float g_du[NU];
__device__ float g_dc[NC];
__device__ float g_colpart[512 * NC];
__device__ float g_colpart2[8 * NC];
__device__ float g_W2[D * D];

// ---------------- helpers ----------------
__device__ __forceinline__ uint32_t smem_u32(const void* p) {
    uint32_t a;
    asm("{ .reg .u64 t; cvta.to.shared.u64 t, %1; cvt.u32.u64 %0, t; }" : "=r"(a) : "l"(p));
    return a;
}
__device__ __forceinline__ void cp16(uint32_t dst, const void* src) {
    asm volatile("cp.async.cg.shared.global [%0], [%1], 16;" :: "r"(dst), "l"(src));
}
#define CP_COMMIT() asm volatile("cp.async.commit_group;" ::: "memory")
#define CP_WAIT2()  asm volatile("cp.async.wait_group 2;" ::: "memory")

__device__ __forceinline__ uint32_t tf32_rna(float x) {
    uint32_t r;
    asm("cvt.rna.tf32.f32 %0, %1;" : "=r"(r) : "f"(x));
    return r;
}
__device__ __forceinline__ float uif(uint32_t x) { return __uint_as_float(x); }

// D = A(16x8, tf32) @ B(8x8, tf32) + D, f32 accum
__device__ __forceinline__ void mma8(float* c, uint32_t a0, uint32_t a1,
                                     uint32_t a2, uint32_t a3,
                                     uint32_t b0, uint32_t b1) {
    asm volatile(
        "mma.sync.aligned.m16n8k8.row.col.f32.tf32.tf32.f32 "
        "{%0,%1,%2,%3}, {%4,%5,%6,%7}, {%8,%9}, {%0,%1,%2,%3};"
        : "+f"(c[0]), "+f"(c[1]), "+f"(c[2]), "+f"(c[3])
        : "r"(a0), "r"(a1), "r"(a2), "r"(a3), "r"(b0), "r"(b1));
}

// ---------------- tiny: W2 = proj_u @ weight_c ----------------
__global__ void k_w2(const float* __restrict__ proj_u,
                     const float* __restrict__ weight_c) {
    int i = threadIdx.x >> 5, j = threadIdx.x & 31;
    float s = 0.f;
#pragma unroll
    for (int k = 0; k < 32; k++) s += proj_u[i * 32 + k] * weight_c[k * 32 + j];
    g_W2[i * 32 + j] = s;
}

// ---------------- rowsums adj_uu / adj_cc -> rsqrt(1+rowsum) ----------------
__global__ void k_rowsum(const float* __restrict__ adj_uu,
                         const float* __restrict__ adj_cc) {
    int row = blockIdx.x;
    const float* A = (blockIdx.y == 0) ? adj_uu : adj_cc;
    float* out = (blockIdx.y == 0) ? g_dinv_uu : g_dinv_cc;
    const float4* p = (const float4*)(A + (size_t)row * NK);
    float s = 0.f;
#pragma unroll
    for (int i = threadIdx.x; i < NK / 4; i += 256) {
        float4 v = p[i];
        s += (v.x + v.y) + (v.z + v.w);
    }
#pragma unroll
    for (int o = 16; o; o >>= 1) s += __shfl_xor_sync(0xffffffffu, s, o);
    __shared__ float sm[8];
    if ((threadIdx.x & 31) == 0) sm[threadIdx.x >> 5] = s;
    __syncthreads();
    if (threadIdx.x == 0) {
        float t = 0.f;
#pragma unroll
        for (int i = 0; i < 8; i++) t += sm[i];
        out[row] = rsqrtf(1.0f + t);
    }
}

// ---------------- adj_uc: row sums -> du, colsum partials ----------------
__global__ void k_uc_sums(const float* __restrict__ adj_uc) {
    int tid = threadIdx.x;
    int m0 = blockIdx.x * 16;
    float4 colacc[8];
#pragma unroll
    for (int i = 0; i < 8; i++) colacc[i] = make_float4(0.f, 0.f, 0.f, 0.f);
    __shared__ float sm[8];
    for (int r = 0; r < 16; r++) {
        const float4* p = (const float4*)(adj_uc + (size_t)(m0 + r) * NK);
        float rs = 0.f;
#pragma unroll
        for (int i = 0; i < 8; i++) {
            float4 v = p[tid + i * 256];
            colacc[i].x += v.x; colacc[i].y += v.y;
            colacc[i].z += v.z; colacc[i].w += v.w;
            rs += (v.x + v.y) + (v.z + v.w);
        }
#pragma unroll
        for (int o = 16; o; o >>= 1) rs += __shfl_xor_sync(0xffffffffu, rs, o);
        __syncthreads();
        if ((tid & 31) == 0) sm[tid >> 5] = rs;
        __syncthreads();
        if (tid == 0) {
            float t = 0.f;
#pragma unroll
            for (int i = 0; i < 8; i++) t += sm[i];
            g_du[m0 + r] = rsqrtf(t);
        }
    }
    float4* cp = (float4*)(g_colpart + (size_t)blockIdx.x * NC);
#pragma unroll
    for (int i = 0; i < 8; i++) cp[tid + i * 256] = colacc[i];
}

// ---------------- colsum reduce (2-stage, deterministic) ----------------
__global__ void k_dc1() {
    int rc = blockIdx.x >> 5;
    int c = (blockIdx.x & 31) * 256 + threadIdx.x;
    float a0 = 0.f, a1 = 0.f, a2 = 0.f, a3 = 0.f;
#pragma unroll 4
    for (int r = rc * 64; r < rc * 64 + 64; r += 4) {
        a0 += g_colpart[(size_t)(r + 0) * NC + c];
        a1 += g_colpart[(size_t)(r + 1) * NC + c];
        a2 += g_colpart[(size_t)(r + 2) * NC + c];
        a3 += g_colpart[(size_t)(r + 3) * NC + c];
    }
    g_colpart2[(size_t)rc * NC + c] = (a0 + a1) + (a2 + a3);
}
__global__ void k_dc2() {
    int c = blockIdx.x * 256 + threadIdx.x;
    float s = 0.f;
#pragma unroll
    for (int r = 0; r < 8; r++) s += g_colpart2[(size_t)r * NC + c];
    g_dc[c] = rsqrtf(s);
}

// ---------------- build pre-split, pre-padded B tiles ----------------
// B[k][n] = scale_k * support[k][n], split into tf32 hi/lo (rna), pitch 36.
__global__ void k_build_b(const float* __restrict__ X_U,
                          const float* __restrict__ X_C,
                          const float* __restrict__ weight_s) {
    __shared__ float Ws[1024];
    int which = blockIdx.y;
    int tid = threadIdx.x;  // 256
    if (which == 2) { for (int i = tid; i < 1024; i += 256) Ws[i] = g_W2[i]; }
    else            { for (int i = tid; i < 1024; i += 256) Ws[i] = weight_s[i]; }
    __syncthreads();

    int row = blockIdx.x * 8 + (tid >> 5);  // global k
    int n = tid & 31;
    const float* X = (which == 1) ? X_C : X_U;
    const float* xr = X + (size_t)row * 32;
    float s = 0.f;
#pragma unroll
    for (int k = 0; k < 32; k++) s += xr[k] * Ws[k * 32 + n];

    float scale;
    if (which == 0)      scale = g_dinv_uu[row];
    else if (which == 1) scale = g_dinv_cc[row];
    else                 scale = g_dc[row];
    float a = scale * s;
    uint32_t hb = tf32_rna(a);
    float lf = a - uif(hb);
    uint32_t lb = tf32_rna(lf);

    int tile = row >> 5, kk = row & 31;
    size_t base = ((size_t)which * 256 + tile) * 2304;
    g_Bt[base + (size_t)kk * 36 + n] = uif(hb);
    g_Bt[base + 1152 + (size_t)kk * 36 + n] = uif(lb);
}

// ---------------- tensor-core 3xTF32 SpMM: out = rowscale ⊙ (A @ T) ----------------
// 384 CTAs (3 mats x 128 M-tiles of 64), 128 thr. Warp = m16 slab (rows wid*16..+15).
// A: gmem->reg fragment loads, 1-chunk prefetch. B: 4-stage cp.async ring from g_Bt.
#define NCH 256
__global__ void __launch_bounds__(128) k_tc(
    const float* __restrict__ adj_uu, const float* __restrict__ adj_cc,
    const float* __restrict__ adj_uc, float* __restrict__ out_u) {
    __shared__ float Bs[4 * 2304];  // 36 KB: 4 stages x [hi 32x36 | lo 32x36]

    int tid = threadIdx.x, wid = tid >> 5, lane = tid & 31;
    int mat = blockIdx.x >> 7, mb = blockIdx.x & 127;
    int m0 = mb * 64;

    const float* A;
    const float* rowscale;
    float* out;
    if (mat == 0)      { A = adj_uu; rowscale = g_dinv_uu; out = out_u; }
    else if (mat == 1) { A = adj_cc; rowscale = g_dinv_cc; out = g_c1; }
    else               { A = adj_uc; rowscale = g_du;      out = g_c2; }

    const float* Bg = g_Bt + (size_t)mat * 256 * 2304;
    uint32_t bs0 = smem_u32(Bs);

    int r0 = m0 + wid * 16;
    int rA = r0 + (lane >> 2);          // rows for a0/a2
    int cA = lane & 3;                  // col offset within 8-k step
    const float* Ap0 = A + (size_t)rA * NK + cA;
    const float* Ap1 = Ap0 + (size_t)8 * NK;  // rows +8 for a1/a3

    // B stage prefetch: chunks 0,1,2
#pragma unroll
    for (int pc = 0; pc < 3; pc++) {
        const char* src = (const char*)(Bg + (size_t)pc * 2304);
        uint32_t dst = bs0 + (uint32_t)pc * 9216;
        for (int i = tid; i < 576; i += 128) cp16(dst + (uint32_t)i * 16, src + i * 16);
        CP_COMMIT();
    }

    // A chunk 0 into cur
    float cur[16], nxt[16];
#pragma unroll
    for (int ks = 0; ks < 4; ks++) {
        int c = ks * 8;
        cur[ks * 4 + 0] = Ap0[c];
        cur[ks * 4 + 1] = Ap1[c];
        cur[ks * 4 + 2] = Ap0[c + 4];
        cur[ks * 4 + 3] = Ap1[c + 4];
    }

    float acc[16];
#pragma unroll
    for (int i = 0; i < 16; i++) acc[i] = 0.f;

    for (int t = 0; t < NCH; t++) {
        CP_WAIT2();
        __syncthreads();

        // prefetch A chunk t+1
        if (t + 1 < NCH) {
            const float* An0 = Ap0 + (t + 1) * 32;
            const float* An1 = Ap1 + (t + 1) * 32;
#pragma unroll
            for (int ks = 0; ks < 4; ks++) {
                int c = ks * 8;
                nxt[ks * 4 + 0] = An0[c];
                nxt[ks * 4 + 1] = An1[c];
                nxt[ks * 4 + 2] = An0[c + 4];
                nxt[ks * 4 + 3] = An1[c + 4];
            }
        }

        const float* Bst = Bs + (t & 3) * 2304;
#pragma unroll
        for (int ks = 0; ks < 4; ks++) {
            // A fragments hi/lo
            uint32_t ah[4], al[4];
#pragma unroll
            for (int j = 0; j < 4; j++) {
                float v = cur[ks * 4 + j];
                ah[j] = tf32_rna(v);
                al[j] = tf32_rna(v - uif(ah[j]));
            }
            int kb = ks * 8 + (lane & 3);
            int nb = lane >> 2;
#pragma unroll
            for (int nt = 0; nt < 4; nt++) {
                uint32_t bh0 = __float_as_uint(Bst[kb * 36 + nt * 8 + nb]);
                uint32_t bh1 = __float_as_uint(Bst[(kb + 4) * 36 + nt * 8 + nb]);
                uint32_t bl0 = __float_as_uint(Bst[1152 + kb * 36 + nt * 8 + nb]);
                uint32_t bl1 = __float_as_uint(Bst[1152 + (kb + 4) * 36 + nt * 8 + nb]);
                float* c = acc + nt * 4;
                mma8(c, ah[0], ah[1], ah[2], ah[3], bh0, bh1);
                mma8(c, al[0], al[1], al[2], al[3], bh0, bh1);
                mma8(c, ah[0], ah[1], ah[2], ah[3], bl0, bl1);
            }
        }

        // stream next B chunk into the stage just freed ((t+3)&3 == (t-1)&3)
        if (t + 3 < NCH) {
            const char* src = (const char*)(Bg + (size_t)(t + 3) * 2304);
            uint32_t dst = bs0 + (uint32_t)((t + 3) & 3) * 9216;
            for (int i = tid; i < 576; i += 128) cp16(dst + (uint32_t)i * 16, src + i * 16);
        }
        CP_COMMIT();

#pragma unroll
        for (int i = 0; i < 16; i++) cur[i] = nxt[i];
    }

    // epilogue: rowscale + store
    int row0 = rA;
    int row1 = rA + 8;
    float s0 = rowscale[row0];
    float s1 = rowscale[row1];
#pragma unroll
    for (int nt = 0; nt < 4; nt++) {
        int col = nt * 8 + 2 * (lane & 3);
        float2 v0 = make_float2(s0 * acc[nt * 4 + 0], s0 * acc[nt * 4 + 1]);
        float2 v1 = make_float2(s1 * acc[nt * 4 + 2], s1 * acc[nt * 4 + 3]);
        *(float2*)(out + (size_t)row0 * 32 + col) = v0;
        *(float2*)(out + (size_t)row1 * 32 + col) = v1;
    }
}

// ---------------- attention + softmax + outputs ----------------
__global__ void k_attn(const float* __restrict__ X_C,
                       const float* __restrict__ W_lin,
                       const float* __restrict__ a_vec,
                       float* __restrict__ out) {
    __shared__ float Ws[64 * 32];
    __shared__ float av[32];
    int tid = threadIdx.x;  // 256
    for (int i = tid; i < 2048; i += 256) Ws[i] = W_lin[i];
    if (tid < 32) av[tid] = a_vec[tid];
    __syncthreads();

    int lane = tid & 31;
    int row = blockIdx.x * 8 + (tid >> 5);

    float c1v = g_c1[(size_t)row * 32 + lane];
    float c2v = g_c2[(size_t)row * 32 + lane];
    float xcv = X_C[(size_t)row * 32 + lane];

    float h1 = 0.f, h2 = 0.f;
#pragma unroll
    for (int k = 0; k < 32; k++) {
        float u1 = __shfl_sync(0xffffffffu, c1v, k);
        float u2 = __shfl_sync(0xffffffffu, c2v, k);
        float w0 = Ws[k * 32 + lane];
        h1 = fmaf(u1, w0, h1);
        h2 = fmaf(u2, w0, h2);
    }
#pragma unroll
    for (int k = 0; k < 32; k++) {
        float ux = __shfl_sync(0xffffffffu, xcv, k);
        float w1 = Ws[(32 + k) * 32 + lane];
        h1 = fmaf(ux, w1, h1);
        h2 = fmaf(ux, w1, h2);
    }
    float t1 = fmaxf(h1, 0.f) * av[lane];
    float t2 = fmaxf(h2, 0.f) * av[lane];
#pragma unroll
    for (int o = 16; o; o >>= 1) {
        t1 += __shfl_xor_sync(0xffffffffu, t1, o);
        t2 += __shfl_xor_sync(0xffffffffu, t2, o);
    }
    float m = fmaxf(t1, t2);
    float e1 = expf(t1 - m), e2 = expf(t2 - m);
    float inv = 1.f / (e1 + e2);
    float yc = (e1 * inv) * c1v;
    float yu = (e2 * inv) * c2v;

    size_t idx = (size_t)row * 32 + lane;
    out[262144 + idx] = yc + yu;
    out[524288 + idx] = yc;
    out[786432 + idx] = yu;
}

// ---------------- launch ----------------
extern "C" void kernel_launch(void* const* d_in, const int* in_sizes, int n_in,
                              void* d_out, int out_size) {
    const float* X_U      = (const float*)d_in[0];
    const float* X_C      = (const float*)d_in[1];
    const float* adj_uu   = (const float*)d_in[2];
    const float* adj_uc   = (const float*)d_in[3];
    const float* adj_cc   = (const float*)d_in[4];
    const float* weight_s = (const float*)d_in[5];
    const float* proj_u   = (const float*)d_in[6];
    const float* weight_c = (const float*)d_in[8];
    const float* W_lin    = (const float*)d_in[9];
    const float* a_vec    = (const float*)d_in[10];
    float* out = (float*)d_out;

    k_w2<<<1, 1024>>>(proj_u, weight_c);
    k_rowsum<<<dim3(8192, 2), 256>>>(adj_uu, adj_cc);
    k_uc_sums<<<512, 256>>>(adj_uc);
    k_dc1<<<256, 256>>>();
    k_dc2<<<32, 256>>>();
    k_build_b<<<dim3(1024, 3), 256>>>(X_U, X_C, weight_s);
    k_tc<<<384, 128>>>(adj_uu, adj_cc, adj_uc, out);
    k_attn<<<1024, 256>>>(X_C, W_lin, a_vec, out);
}

// round 5
// speedup vs baseline: 2.6943x; 1.6588x over previous
#include <cuda_runtime.h>
#include <cstdint>

#define NU 8192
#define NC 8192
#define NK 8192
#define D  32

// ---------------- scratch ----------------
// B tiles in mma-fragment order: per (mat, ktile): 512 x float4(bh0,bh1,bl0,bl1) = 8KB
__device__ float4 g_Bt[3 * 256 * 512];
__device__ float g_part[2 * 3 * 8192 * 32];  // k-split partials
__device__ float g_c1[NC * D];
__device__ float g_c2[NC * D];
__device__ float g_dinv_uu[NU];
__device__ float g_dinv_cc[NC];
__device__ float g_du[NU];
__device__ float g_dc[NC];
__device__ float g_colpart[512 * NC];
__device__ float g_colpart2[8 * NC];

// ---------------- helpers ----------------
__device__ __forceinline__ uint32_t smem_u32(const void* p) {
    uint32_t a;
    asm("{ .reg .u64 t; cvta.to.shared.u64 t, %1; cvt.u32.u64 %0, t; }" : "=r"(a) : "l"(p));
    return a;
}
__device__ __forceinline__ void cp16(uint32_t dst, const void* src) {
    asm volatile("cp.async.cg.shared.global [%0], [%1], 16;" :: "r"(dst), "l"(src));
}
#define CP_COMMIT() asm volatile("cp.async.commit_group;" ::: "memory")
#define CP_WAIT2()  asm volatile("cp.async.wait_group 2;" ::: "memory")

__device__ __forceinline__ uint32_t tf32_rna(float x) {
    uint32_t r;
    asm("cvt.rna.tf32.f32 %0, %1;" : "=r"(r) : "f"(x));
    return r;
}
__device__ __forceinline__ float uif(uint32_t x) { return __uint_as_float(x); }

__device__ __forceinline__ void mma8(float* c, uint32_t a0, uint32_t a1,
                                     uint32_t a2, uint32_t a3,
                                     uint32_t b0, uint32_t b1) {
    asm volatile(
        "mma.sync.aligned.m16n8k8.row.col.f32.tf32.tf32.f32 "
        "{%0,%1,%2,%3}, {%4,%5,%6,%7}, {%8,%9}, {%0,%1,%2,%3};"
        : "+f"(c[0]), "+f"(c[1]), "+f"(c[2]), "+f"(c[3])
        : "r"(a0), "r"(a1), "r"(a2), "r"(a3), "r"(b0), "r"(b1));
}

// ---------------- rowsums adj_uu / adj_cc -> rsqrt(1+rowsum) ----------------
__global__ void k_rowsum(const float* __restrict__ adj_uu,
                         const float* __restrict__ adj_cc) {
    int row = blockIdx.x;
    const float* A = (blockIdx.y == 0) ? adj_uu : adj_cc;
    float* out = (blockIdx.y == 0) ? g_dinv_uu : g_dinv_cc;
    const float4* p = (const float4*)(A + (size_t)row * NK);
    float s = 0.f;
#pragma unroll
    for (int i = threadIdx.x; i < NK / 4; i += 256) {
        float4 v = p[i];
        s += (v.x + v.y) + (v.z + v.w);
    }
#pragma unroll
    for (int o = 16; o; o >>= 1) s += __shfl_xor_sync(0xffffffffu, s, o);
    __shared__ float sm[8];
    if ((threadIdx.x & 31) == 0) sm[threadIdx.x >> 5] = s;
    __syncthreads();
    if (threadIdx.x == 0) {
        float t = 0.f;
#pragma unroll
        for (int i = 0; i < 8; i++) t += sm[i];
        out[row] = rsqrtf(1.0f + t);
    }
}

// ---------------- adj_uc: row sums -> du, colsum partials ----------------
__global__ void k_uc_sums(const float* __restrict__ adj_uc) {
    int tid = threadIdx.x;
    int m0 = blockIdx.x * 16;
    float4 colacc[8];
#pragma unroll
    for (int i = 0; i < 8; i++) colacc[i] = make_float4(0.f, 0.f, 0.f, 0.f);
    __shared__ float sm[8];
    for (int r = 0; r < 16; r++) {
        const float4* p = (const float4*)(adj_uc + (size_t)(m0 + r) * NK);
        float rs = 0.f;
#pragma unroll
        for (int i = 0; i < 8; i++) {
            float4 v = p[tid + i * 256];
            colacc[i].x += v.x; colacc[i].y += v.y;
            colacc[i].z += v.z; colacc[i].w += v.w;
            rs += (v.x + v.y) + (v.z + v.w);
        }
#pragma unroll
        for (int o = 16; o; o >>= 1) rs += __shfl_xor_sync(0xffffffffu, rs, o);
        __syncthreads();
        if ((tid & 31) == 0) sm[tid >> 5] = rs;
        __syncthreads();
        if (tid == 0) {
            float t = 0.f;
#pragma unroll
            for (int i = 0; i < 8; i++) t += sm[i];
            g_du[m0 + r] = rsqrtf(t);
        }
    }
    float4* cp = (float4*)(g_colpart + (size_t)blockIdx.x * NC);
#pragma unroll
    for (int i = 0; i < 8; i++) cp[tid + i * 256] = colacc[i];
}

// ---------------- colsum reduce (2-stage, deterministic) ----------------
__global__ void k_dc1() {
    int rc = blockIdx.x >> 5;
    int c = (blockIdx.x & 31) * 256 + threadIdx.x;
    float a0 = 0.f, a1 = 0.f, a2 = 0.f, a3 = 0.f;
#pragma unroll 4
    for (int r = rc * 64; r < rc * 64 + 64; r += 4) {
        a0 += g_colpart[(size_t)(r + 0) * NC + c];
        a1 += g_colpart[(size_t)(r + 1) * NC + c];
        a2 += g_colpart[(size_t)(r + 2) * NC + c];
        a3 += g_colpart[(size_t)(r + 3) * NC + c];
    }
    g_colpart2[(size_t)rc * NC + c] = (a0 + a1) + (a2 + a3);
}
__global__ void k_dc2() {
    int c = blockIdx.x * 256 + threadIdx.x;
    float s = 0.f;
#pragma unroll
    for (int r = 0; r < 8; r++) s += g_colpart2[(size_t)r * NC + c];
    g_dc[c] = rsqrtf(s);
}

// ---------------- build B tiles in mma-fragment order ----------------
// One block per (ktile, mat). Computes scaled support S (32k x 32n), then emits
// per (ks,nt,lane) a float4 (bh0, bh1, bl0, bl1) where hi = tf32-rna, lo = residual.
__global__ void k_build_b(const float* __restrict__ X_U,
                          const float* __restrict__ X_C,
                          const float* __restrict__ weight_s,
                          const float* __restrict__ proj_u,
                          const float* __restrict__ weight_c) {
    __shared__ float Ws[1024];
    __shared__ float Xs[1024];
    __shared__ float sup[32 * 33];
    int mat = blockIdx.y;
    int ktile = blockIdx.x;
    int tid = threadIdx.x;  // 256

    // W into smem (mat 2: W2 = proj_u @ weight_c computed inline)
    if (mat == 2) {
#pragma unroll
        for (int e = tid; e < 1024; e += 256) {
            int i = e >> 5, j = e & 31;
            float s = 0.f;
#pragma unroll
            for (int k = 0; k < 32; k++) s += proj_u[i * 32 + k] * weight_c[k * 32 + j];
            Ws[e] = s;
        }
    } else {
#pragma unroll
        for (int e = tid; e < 1024; e += 256) Ws[e] = weight_s[e];
    }
    // X rows ktile*32..+31
    const float* X = (mat == 1) ? X_C : X_U;
#pragma unroll
    for (int e = tid; e < 1024; e += 256) Xs[e] = X[(size_t)ktile * 1024 + e];
    __syncthreads();

    // scaled support
    {
        int k = tid >> 3;
        int nq = (tid & 7) * 4;
        float scale;
        int gk = ktile * 32 + k;
        if (mat == 0)      scale = g_dinv_uu[gk];
        else if (mat == 1) scale = g_dinv_cc[gk];
        else               scale = g_dc[gk];
#pragma unroll
        for (int q = 0; q < 4; q++) {
            int n = nq + q;
            float s = 0.f;
#pragma unroll
            for (int j = 0; j < 32; j++) s += Xs[k * 32 + j] * Ws[j * 32 + n];
            sup[k * 33 + n] = scale * s;
        }
    }
    __syncthreads();

    // fragment emit: 512 float4 entries, 2 per thread
    float4* dst = g_Bt + ((size_t)mat * 256 + ktile) * 512;
#pragma unroll
    for (int it = 0; it < 2; it++) {
        int e = tid + it * 256;
        int lane = e & 31, nt = (e >> 5) & 3, ks = e >> 7;
        int la = lane & 3, gr = lane >> 2;
        int k0 = ks * 8 + la, n = nt * 8 + gr;
        float b0 = sup[k0 * 33 + n];
        float b1 = sup[(k0 + 4) * 33 + n];
        float h0 = uif(tf32_rna(b0));
        float h1 = uif(tf32_rna(b1));
        dst[e] = make_float4(h0, h1, b0 - h0, b1 - h1);
    }
}

// ---------------- tensor-core 3xTF32 SpMM, warp=m32, K-split x2 ----------------
// grid 384: blockIdx.x -> mat (x/128), mb ((x%128)>>1), ksp (x&1). 128 thr.
// Partials (unscaled) to g_part; k_fin combines + row-scales.
#define NCH2 128
__global__ void __launch_bounds__(128) k_tc(
    const float* __restrict__ adj_uu, const float* __restrict__ adj_cc,
    const float* __restrict__ adj_uc) {
    __shared__ float4 Bs[4 * 512];  // 32KB: 4 stages x 8KB fragment tiles

    int tid = threadIdx.x, wid = tid >> 5, lane = tid & 31;
    int mat = blockIdx.x >> 7;
    int rem = blockIdx.x & 127;
    int mb = rem >> 1, ksp = rem & 1;
    int m0 = mb * 128;
    int kbase = ksp * NCH2;  // chunk index base

    const float* A = (mat == 0) ? adj_uu : (mat == 1) ? adj_cc : adj_uc;
    const float4* Bg = g_Bt + ((size_t)mat * 256 + kbase) * 512;
    uint32_t bs0 = smem_u32(Bs);

    int rA = m0 + wid * 32 + (lane >> 2);
    int cA = lane & 3;
    const float* Ab = A + (size_t)rA * NK + cA + (size_t)kbase * 32;

    // prefetch B stages 0..2
#pragma unroll
    for (int pc = 0; pc < 3; pc++) {
        const char* src = (const char*)(Bg + (size_t)pc * 512);
        uint32_t dst = bs0 + (uint32_t)pc * 8192;
#pragma unroll
        for (int i = 0; i < 4; i++)
            cp16(dst + (uint32_t)(tid + i * 128) * 16, src + (tid + i * 128) * 16);
        CP_COMMIT();
    }

    // A chunk 0: cur[mt*16 + ks*4 + j], rows rA+mt*16 (+8), cols cA+ks*8 (+4)
    float cur[32], nxt[32];
#pragma unroll
    for (int mt = 0; mt < 2; mt++) {
        const float* r0p = Ab + (size_t)(mt * 16) * NK;
        const float* r1p = r0p + (size_t)8 * NK;
#pragma unroll
        for (int ks = 0; ks < 4; ks++) {
            int c = ks * 8;
            cur[mt * 16 + ks * 4 + 0] = r0p[c];
            cur[mt * 16 + ks * 4 + 1] = r1p[c];
            cur[mt * 16 + ks * 4 + 2] = r0p[c + 4];
            cur[mt * 16 + ks * 4 + 3] = r1p[c + 4];
        }
    }

    float acc[32];
#pragma unroll
    for (int i = 0; i < 32; i++) acc[i] = 0.f;

    for (int t = 0; t < NCH2; t++) {
        CP_WAIT2();
        __syncthreads();

        if (t + 1 < NCH2) {
            const float* An = Ab + (t + 1) * 32;
#pragma unroll
            for (int mt = 0; mt < 2; mt++) {
                const float* r0p = An + (size_t)(mt * 16) * NK;
                const float* r1p = r0p + (size_t)8 * NK;
#pragma unroll
                for (int ks = 0; ks < 4; ks++) {
                    int c = ks * 8;
                    nxt[mt * 16 + ks * 4 + 0] = r0p[c];
                    nxt[mt * 16 + ks * 4 + 1] = r1p[c];
                    nxt[mt * 16 + ks * 4 + 2] = r0p[c + 4];
                    nxt[mt * 16 + ks * 4 + 3] = r1p[c + 4];
                }
            }
        }

        const float4* Bst = Bs + (t & 3) * 512;
#pragma unroll
        for (int ks = 0; ks < 4; ks++) {
            uint32_t ah[8], al[8];
#pragma unroll
            for (int mt = 0; mt < 2; mt++) {
#pragma unroll
                for (int j = 0; j < 4; j++) {
                    float v = cur[mt * 16 + ks * 4 + j];
                    uint32_t h = tf32_rna(v);
                    ah[mt * 4 + j] = h;
                    al[mt * 4 + j] = __float_as_uint(v - uif(h));
                }
            }
#pragma unroll
            for (int nt = 0; nt < 4; nt++) {
                float4 b = Bst[(ks * 4 + nt) * 32 + lane];
                uint32_t bh0 = __float_as_uint(b.x);
                uint32_t bh1 = __float_as_uint(b.y);
                uint32_t bl0 = __float_as_uint(b.z);
                uint32_t bl1 = __float_as_uint(b.w);
#pragma unroll
                for (int mt = 0; mt < 2; mt++) {
                    float* c = acc + mt * 16 + nt * 4;
                    mma8(c, ah[mt * 4 + 0], ah[mt * 4 + 1], ah[mt * 4 + 2], ah[mt * 4 + 3], bh0, bh1);
                    mma8(c, al[mt * 4 + 0], al[mt * 4 + 1], al[mt * 4 + 2], al[mt * 4 + 3], bh0, bh1);
                    mma8(c, ah[mt * 4 + 0], ah[mt * 4 + 1], ah[mt * 4 + 2], ah[mt * 4 + 3], bl0, bl1);
                }
            }
        }

        if (t + 3 < NCH2) {
            const char* src = (const char*)(Bg + (size_t)(t + 3) * 512);
            uint32_t dst = bs0 + (uint32_t)((t + 3) & 3) * 8192;
#pragma unroll
            for (int i = 0; i < 4; i++)
                cp16(dst + (uint32_t)(tid + i * 128) * 16, src + (tid + i * 128) * 16);
        }
        CP_COMMIT();

#pragma unroll
        for (int i = 0; i < 32; i++) cur[i] = nxt[i];
    }

    // partial (unscaled) store
    float* P = g_part + ((size_t)ksp * 3 + mat) * (8192 * 32);
#pragma unroll
    for (int mt = 0; mt < 2; mt++) {
        int row0 = rA + mt * 16;
        int row1 = row0 + 8;
#pragma unroll
        for (int nt = 0; nt < 4; nt++) {
            float* c = acc + mt * 16 + nt * 4;
            int col = nt * 8 + 2 * (lane & 3);
            *(float2*)(P + (size_t)row0 * 32 + col) = make_float2(c[0], c[1]);
            *(float2*)(P + (size_t)row1 * 32 + col) = make_float2(c[2], c[3]);
        }
    }
}

// ---------------- combine K-split partials + row scale ----------------
__global__ void k_fin(float* __restrict__ out_u) {
    int mat = blockIdx.y;
    int idx = blockIdx.x * 256 + threadIdx.x;  // 0..262143
    int row = idx >> 5;
    float scale;
    float* out;
    if (mat == 0)      { scale = g_dinv_uu[row]; out = out_u; }
    else if (mat == 1) { scale = g_dinv_cc[row]; out = g_c1; }
    else               { scale = g_du[row];      out = g_c2; }
    float v = g_part[(size_t)mat * 262144 + idx] +
              g_part[(size_t)(mat + 3) * 262144 + idx];
    out[idx] = scale * v;
}

// ---------------- attention + softmax + outputs ----------------
__global__ void k_attn(const float* __restrict__ X_C,
                       const float* __restrict__ W_lin,
                       const float* __restrict__ a_vec,
                       float* __restrict__ out) {
    __shared__ float Ws[64 * 32];
    __shared__ float av[32];
    int tid = threadIdx.x;  // 256
    for (int i = tid; i < 2048; i += 256) Ws[i] = W_lin[i];
    if (tid < 32) av[tid] = a_vec[tid];
    __syncthreads();

    int lane = tid & 31;
    int row = blockIdx.x * 8 + (tid >> 5);

    float c1v = g_c1[(size_t)row * 32 + lane];
    float c2v = g_c2[(size_t)row * 32 + lane];
    float xcv = X_C[(size_t)row * 32 + lane];

    float h1 = 0.f, h2 = 0.f;
#pragma unroll
    for (int k = 0; k < 32; k++) {
        float u1 = __shfl_sync(0xffffffffu, c1v, k);
        float u2 = __shfl_sync(0xffffffffu, c2v, k);
        float w0 = Ws[k * 32 + lane];
        h1 = fmaf(u1, w0, h1);
        h2 = fmaf(u2, w0, h2);
    }
#pragma unroll
    for (int k = 0; k < 32; k++) {
        float ux = __shfl_sync(0xffffffffu, xcv, k);
        float w1 = Ws[(32 + k) * 32 + lane];
        h1 = fmaf(ux, w1, h1);
        h2 = fmaf(ux, w1, h2);
    }
    float t1 = fmaxf(h1, 0.f) * av[lane];
    float t2 = fmaxf(h2, 0.f) * av[lane];
#pragma unroll
    for (int o = 16; o; o >>= 1) {
        t1 += __shfl_xor_sync(0xffffffffu, t1, o);
        t2 += __shfl_xor_sync(0xffffffffu, t2, o);
    }
    float m = fmaxf(t1, t2);
    float e1 = expf(t1 - m), e2 = expf(t2 - m);
    float inv = 1.f / (e1 + e2);
    float yc = (e1 * inv) * c1v;
    float yu = (e2 * inv) * c2v;

    size_t idx = (size_t)row * 32 + lane;
    out[262144 + idx] = yc + yu;
    out[524288 + idx] = yc;
    out[786432 + idx] = yu;
}

// ---------------- launch ----------------
extern "C" void kernel_launch(void* const* d_in, const int* in_sizes, int n_in,
                              void* d_out, int out_size) {
    const float* X_U      = (const float*)d_in[0];
    const float* X_C      = (const float*)d_in[1];
    const float* adj_uu   = (const float*)d_in[2];
    const float* adj_uc   = (const float*)d_in[3];
    const float* adj_cc   = (const float*)d_in[4];
    const float* weight_s = (const float*)d_in[5];
    const float* proj_u   = (const float*)d_in[6];
    const float* weight_c = (const float*)d_in[8];
    const float* W_lin    = (const float*)d_in[9];
    const float* a_vec    = (const float*)d_in[10];
    float* out = (float*)d_out;

    k_rowsum<<<dim3(8192, 2), 256>>>(adj_uu, adj_cc);           // 1
    k_uc_sums<<<512, 256>>>(adj_uc);                            // 2
    k_dc1<<<256, 256>>>();                                      // 3
    k_dc2<<<32, 256>>>();                                       // 4
    k_build_b<<<dim3(256, 3), 256>>>(X_U, X_C, weight_s, proj_u, weight_c);  // 5
    k_tc<<<384, 128>>>(adj_uu, adj_cc, adj_uc);                 // 6 <- ncu target
    k_fin<<<dim3(1024, 3), 256>>>(out);                         // 7
    k_attn<<<1024, 256>>>(X_C, W_lin, a_vec, out);              // 8
}